// round 14
// baseline (speedup 1.0000x reference)
#include <cuda_runtime.h>
#include <cuda_fp16.h>

#define BB 8
#define TT 512
#define DD 64
#define TILE 32
#define NT (TT / TILE)               // 16 tiles per dim
#define NPAIR (NT * (NT + 1) / 2)    // 136 upper-tri tile pairs

#define SQRT_LOG2E 1.2011224087864498f
#define SGN2 0x80008000u

typedef unsigned long long u64;
typedef __half2 h2;

// Precomputed half-precision operands (written by v_kernel):
__device__ __half g_xh[BB * TT * DD];   // s * x   (256 KB)
__device__ __half g_vh[BB * TT * DD];   // v = xW^T + b (256 KB)

// ---- f32x2 packed helpers ---------------------------------------------------
__device__ __forceinline__ u64 pack2(float lo, float hi) {
    u64 r; asm("mov.b64 %0, {%1, %2};" : "=l"(r) : "f"(lo), "f"(hi)); return r;
}
__device__ __forceinline__ void unpack2(u64 v, float& lo, float& hi) {
    asm("mov.b64 {%0, %1}, %2;" : "=f"(lo), "=f"(hi) : "l"(v));
}
__device__ __forceinline__ u64 add2(u64 a, u64 b) {
    u64 r; asm("add.rn.f32x2 %0, %1, %2;" : "=l"(r) : "l"(a), "l"(b)); return r;
}
__device__ __forceinline__ u64 mul2(u64 a, u64 b) {
    u64 r; asm("mul.rn.f32x2 %0, %1, %2;" : "=l"(r) : "l"(a), "l"(b)); return r;
}
__device__ __forceinline__ u64 fma2(u64 a, u64 b, u64 c) {
    u64 r; asm("fma.rn.f32x2 %0, %1, %2, %3;" : "=l"(r) : "l"(a), "l"(b), "l"(c)); return r;
}

// ---- f16x2 helpers ---------------------------------------------------------
__device__ __forceinline__ h2 u2h(unsigned u) { return *(h2*)&u; }
__device__ __forceinline__ h2 ex2negsq(h2 dif) {
    h2 m = __hmul2(__hneg2(dif), dif);
    unsigned r, u = *(unsigned*)&m;
    asm("ex2.approx.f16x2 %0, %1;" : "=r"(r) : "r"(u));
    return *(h2*)&r;
}

// ---------------------------------------------------------------------------
// Kernel 1: v = x @ W^T + b; emits g_xh = half(s*x), g_vh = half(v).
// ---------------------------------------------------------------------------
#define WSTR 68
__global__ __launch_bounds__(256)
void v_kernel(const float* __restrict__ x, const float* __restrict__ W,
              const float* __restrict__ bias) {
    __shared__ float sWT[DD * WSTR];
    __shared__ float sX[32 * DD];

    int tid = threadIdx.x;
    int row0 = blockIdx.x * 32;

    for (int k = tid; k < DD * DD; k += 256) {
        int e = k >> 6, d = k & 63;
        sWT[d * WSTR + e] = W[k];
    }
    for (int k = tid; k < 32 * DD; k += 256)
        sX[k] = x[row0 * DD + k];
    __syncthreads();

#pragma unroll
    for (int k = 0; k < 4; k++) {
        int lin = tid + 256 * k;
        int r = lin >> 5, q = lin & 31;
        float a0 = sX[r * DD + 2 * q];
        float a1 = sX[r * DD + 2 * q + 1];
        h2 hv = __floats2half2_rn(SQRT_LOG2E * a0, SQRT_LOG2E * a1);
        ((unsigned*)g_xh)[(row0 + r) * 32 + q] = *(unsigned*)&hv;
    }

    int eg = tid & 15;
    int rs = tid >> 4;
    float4 b4 = *(const float4*)&bias[4 * eg];
    u64 acc0a = pack2(b4.x, b4.y), acc0b = pack2(b4.z, b4.w);
    u64 acc1a = acc0a, acc1b = acc0b;

#pragma unroll 8
    for (int d = 0; d < DD; d++) {
        const float* wp = &sWT[d * WSTR + 4 * eg];
        u64 wA = *(const u64*)&wp[0];
        u64 wB = *(const u64*)&wp[2];
        float x0 = sX[rs * DD + d];
        float x1 = sX[(rs + 16) * DD + d];
        u64 x0p = pack2(x0, x0), x1p = pack2(x1, x1);
        acc0a = fma2(x0p, wA, acc0a);
        acc0b = fma2(x0p, wB, acc0b);
        acc1a = fma2(x1p, wA, acc1a);
        acc1b = fma2(x1p, wB, acc1b);
    }
    float o0, o1, o2, o3;
    uint2 st;
    unpack2(acc0a, o0, o1); unpack2(acc0b, o2, o3);
    { h2 pA = __floats2half2_rn(o0, o1), pB = __floats2half2_rn(o2, o3);
      st.x = *(unsigned*)&pA; st.y = *(unsigned*)&pB; }
    *(uint2*)&g_vh[(row0 + rs) * DD + 4 * eg] = st;
    unpack2(acc1a, o0, o1); unpack2(acc1b, o2, o3);
    { h2 pA = __floats2half2_rn(o0, o1), pB = __floats2half2_rn(o2, o3);
      st.x = *(unsigned*)&pA; st.y = *(unsigned*)&pB; }
    *(uint2*)&g_vh[(row0 + rs + 16) * DD + 4 * eg] = st;
}

// ---------------------------------------------------------------------------
// Kernel 2: pairwise RBF, HYBRID exp:
//  - d in [0,52): f16x2 MUFU path (13 u-slots of 4 d)
//  - d in [52,64): f32x2 POLYNOMIAL path on the FMA pipe (no MUFU):
//      t = dif^2; z = t + 1.5*2^23 (RN -> n in mantissa); f = t - n;
//      2^-f deg-4 Taylor; scale 2^-n = bits(0x3F800000 - (z<<23)).
// Balances MUFU (~26K cyc) against FMA (~27K cyc), both below the old 32K
// MUFU element-rate floor.
// ---------------------------------------------------------------------------
#define OFF_VI  2048
#define OFF_NXJ 4096
#define OFF_VJ  6144
#define PDP 6            // poly d-pairs (12 d)

__global__ __launch_bounds__(256, 4)
void rbf_kernel(float* __restrict__ out) {
    __shared__ __align__(16) __half Sh[8192];       // h2: XI | VI | NXJ | VJ
    __shared__ __align__(16) float XI32[32 * 12];   // f32 slice, d in [52,64)
    __shared__ __align__(16) float VI32[32 * 12];
    __shared__ __align__(16) float NXJ32[32 * 14];  // stride 14: conflict-free
    __shared__ __align__(16) float VJ32[32 * 14];

    int b = blockIdx.y;
    int p = blockIdx.x;
    int ti = 0, rem = p;
    while (rem >= NT - ti) { rem -= NT - ti; ti++; }
    int tj = ti + rem;
    int i0 = ti * TILE, j0 = tj * TILE;

    int tid = threadIdx.x;
    const unsigned* gx = (const unsigned*)g_xh;
    const unsigned* gv = (const unsigned*)g_vh;
    unsigned* S32 = (unsigned*)Sh;
    int baseI = (b * TT + i0) * 32;
    int baseJ = (b * TT + j0) * 32;

    // h2 staging (same as R12)
    {
        int r = tid >> 3, q0 = (tid & 7) * 4;
        int lin = r * 32 + q0;
        uint4 xi4 = *(const uint4*)&gx[baseI + lin];
        uint4 vi4 = *(const uint4*)&gv[baseI + lin];
        uint4 xj4 = *(const uint4*)&gx[baseJ + lin];
        uint4 vj4 = *(const uint4*)&gv[baseJ + lin];

        *(uint4*)&S32[lin] = xi4;
        *(uint4*)&S32[(OFF_VI >> 1) + lin] = vi4;

        int msk = r & 15;
        int u0 = (q0 >> 1) ^ msk;
        int u1 = u0 ^ 1;
        *(uint2*)&S32[(OFF_NXJ >> 1) + r * 32 + 2 * u0] =
            make_uint2(xj4.x ^ SGN2, xj4.y ^ SGN2);
        *(uint2*)&S32[(OFF_NXJ >> 1) + r * 32 + 2 * u1] =
            make_uint2(xj4.z ^ SGN2, xj4.w ^ SGN2);
        *(uint2*)&S32[(OFF_VJ >> 1) + r * 32 + 2 * u0] = make_uint2(vj4.x, vj4.y);
        *(uint2*)&S32[(OFF_VJ >> 1) + r * 32 + 2 * u1] = make_uint2(vj4.z, vj4.w);
    }
    // f32 staging for d in [52,64): quads 26..31 per row
    for (int k = tid; k < 192; k += 256) {
        int r = k / 6, qq = k - 6 * r;             // row, quad-within-slice
        unsigned uxi = gx[baseI + r * 32 + 26 + qq];
        unsigned uvi = gv[baseI + r * 32 + 26 + qq];
        unsigned uxj = gx[baseJ + r * 32 + 26 + qq];
        unsigned uvj = gv[baseJ + r * 32 + 26 + qq];
        float2 f;
        f = __half22float2(u2h(uxi)); *(float2*)&XI32[r * 12 + 2 * qq] = f;
        f = __half22float2(u2h(uvi)); *(float2*)&VI32[r * 12 + 2 * qq] = f;
        f = __half22float2(u2h(uxj));
        *(float2*)&NXJ32[r * 14 + 2 * qq] = make_float2(-f.x, -f.y);
        f = __half22float2(u2h(uvj)); *(float2*)&VJ32[r * 14 + 2 * qq] = f;
    }
    __syncthreads();

    int tx = tid & 15, ty = tid >> 4;
    const __half* pi = Sh + 2 * ty * 64;
    const __half* pj = Sh + OFF_NXJ + tx * 64;

    float denF[2][2], niF[2][2], njF[2][2];
#pragma unroll
    for (int r = 0; r < 2; r++)
#pragma unroll
        for (int c = 0; c < 2; c++) { denF[r][c] = 0.f; niF[r][c] = 0.f; njF[r][c] = 0.f; }

    // ---- h2 MUFU phase: u-slots 0..12 (d 0..51), chunks {4,4,4,1} ----
#pragma unroll
    for (int ch = 0; ch < 4; ch++) {
        h2 dH[2][2], nH[2][2], qH[2][2];
        h2 z = __float2half2_rn(0.f);
#pragma unroll
        for (int r = 0; r < 2; r++)
#pragma unroll
            for (int c = 0; c < 2; c++) { dH[r][c] = z; nH[r][c] = z; qH[r][c] = z; }

#pragma unroll
        for (int s = 0; s < 4; s++) {
            int u = ch * 4 + s;
            if (u >= 13) break;               // compile-time pruned
            int uj = u ^ tx;

            uint2 fiA = *(const uint2*)(pi + 4 * u);
            uint2 fiB = *(const uint2*)(pi + 64 + 4 * u);
            uint2 fvA = *(const uint2*)(pi + OFF_VI + 4 * u);
            uint2 fvB = *(const uint2*)(pi + OFF_VI + 64 + 4 * u);
            uint2 njA = *(const uint2*)(pj + 4 * uj);
            uint2 njB = *(const uint2*)(pj + 1024 + 4 * uj);
            uint2 jvA = *(const uint2*)(pj + 2048 + 4 * uj);
            uint2 jvB = *(const uint2*)(pj + 2048 + 1024 + 4 * uj);

            h2 fi[2][2] = {{u2h(fiA.x), u2h(fiA.y)}, {u2h(fiB.x), u2h(fiB.y)}};
            h2 fv[2][2] = {{u2h(fvA.x), u2h(fvA.y)}, {u2h(fvB.x), u2h(fvB.y)}};
            h2 nj[2][2] = {{u2h(njA.x), u2h(njA.y)}, {u2h(njB.x), u2h(njB.y)}};
            h2 jv[2][2] = {{u2h(jvA.x), u2h(jvA.y)}, {u2h(jvB.x), u2h(jvB.y)}};

#pragma unroll
            for (int r = 0; r < 2; r++)
#pragma unroll
                for (int c = 0; c < 2; c++)
#pragma unroll
                    for (int s2 = 0; s2 < 2; s2++) {
                        h2 dif = __hadd2(fi[r][s2], nj[c][s2]);
                        h2 e   = ex2negsq(dif);
                        dH[r][c] = __hadd2(dH[r][c], e);
                        nH[r][c] = __hfma2(e, fv[r][s2], nH[r][c]);
                        qH[r][c] = __hfma2(e, jv[c][s2], qH[r][c]);
                    }
        }

#pragma unroll
        for (int r = 0; r < 2; r++)
#pragma unroll
            for (int c = 0; c < 2; c++) {
                float2 t;
                t = __half22float2(dH[r][c]); denF[r][c] += t.x + t.y;
                t = __half22float2(nH[r][c]); niF[r][c]  += t.x + t.y;
                t = __half22float2(qH[r][c]); njF[r][c]  += t.x + t.y;
            }
    }

    // ---- f32x2 POLY phase: d in [52,64), no MUFU ----
    {
        u64 MAG  = pack2( 12582912.f,  12582912.f);   // 1.5 * 2^23
        u64 NMAG = pack2(-12582912.f, -12582912.f);
        u64 M1   = pack2(-1.f, -1.f);
        u64 C4 = pack2( 0.00961813f,  0.00961813f);   // Taylor of 2^-f
        u64 C3 = pack2(-0.05550411f, -0.05550411f);
        u64 C2 = pack2( 0.24022651f,  0.24022651f);
        u64 C1 = pack2(-0.69314718f, -0.69314718f);
        u64 C0 = pack2(1.f, 1.f);

        const float* pir0 = XI32 + 2 * ty * 12;
        const float* pir1 = pir0 + 12;
        const float* pvr0 = VI32 + 2 * ty * 12;
        const float* pvr1 = pvr0 + 12;
        const float* pjc0 = NXJ32 + tx * 14;
        const float* pjc1 = NXJ32 + (tx + 16) * 14;
        const float* pwc0 = VJ32 + tx * 14;
        const float* pwc1 = VJ32 + (tx + 16) * 14;

        u64 pdA[2][2], pnA[2][2], pqA[2][2];
#pragma unroll
        for (int r = 0; r < 2; r++)
#pragma unroll
            for (int c = 0; c < 2; c++) { pdA[r][c] = 0ULL; pnA[r][c] = 0ULL; pqA[r][c] = 0ULL; }

#pragma unroll
        for (int dp = 0; dp < PDP; dp++) {
            u64 fi[2], fv[2], nj[2], jv[2];
            fi[0] = *(const u64*)(pir0 + 2 * dp);
            fi[1] = *(const u64*)(pir1 + 2 * dp);
            fv[0] = *(const u64*)(pvr0 + 2 * dp);
            fv[1] = *(const u64*)(pvr1 + 2 * dp);
            nj[0] = *(const u64*)(pjc0 + 2 * dp);
            nj[1] = *(const u64*)(pjc1 + 2 * dp);
            jv[0] = *(const u64*)(pwc0 + 2 * dp);
            jv[1] = *(const u64*)(pwc1 + 2 * dp);

#pragma unroll
            for (int r = 0; r < 2; r++)
#pragma unroll
                for (int c = 0; c < 2; c++) {
                    u64 dif = add2(fi[r], nj[c]);     // s*(xi-xj)
                    u64 t   = mul2(dif, dif);         // t >= 0
                    u64 z   = add2(t, MAG);           // n = round(t) in mantissa
                    u64 nf  = add2(z, NMAG);          // n as float, exact
                    u64 f   = fma2(nf, M1, t);        // f = t - n in [-0.5,0.5]
                    u64 pp  = fma2(C4, f, C3);
                    pp = fma2(pp, f, C2);
                    pp = fma2(pp, f, C1);
                    pp = fma2(pp, f, C0);             // 2^-f
                    unsigned zl = (unsigned)z, zh = (unsigned)(z >> 32);
                    unsigned sl = 0x3F800000u - (zl << 23);   // bits of 2^-n
                    unsigned sh = 0x3F800000u - (zh << 23);
                    u64 s2 = ((u64)sh << 32) | (u64)sl;
                    u64 e = mul2(pp, s2);             // exp2(-t), f32 pair
                    pdA[r][c] = add2(pdA[r][c], e);
                    pnA[r][c] = fma2(e, fv[r], pnA[r][c]);
                    pqA[r][c] = fma2(e, jv[c], pqA[r][c]);
                }
        }

#pragma unroll
        for (int r = 0; r < 2; r++)
#pragma unroll
            for (int c = 0; c < 2; c++) {
                float lo, hi;
                unpack2(pdA[r][c], lo, hi); denF[r][c] += lo + hi;
                unpack2(pnA[r][c], lo, hi); niF[r][c]  += lo + hi;
                unpack2(pqA[r][c], lo, hi); njF[r][c]  += lo + hi;
            }
    }

    float* ob = out + (size_t)b * TT * TT;

#pragma unroll
    for (int r = 0; r < 2; r++) {
        int gi = i0 + 2 * ty + r;
#pragma unroll
        for (int c = 0; c < 2; c++) {
            int gj = j0 + tx + 16 * c;
            float rc;
            asm("rcp.approx.ftz.f32 %0, %1;" : "=f"(rc) : "f"(denF[r][c]));
            ob[(size_t)gi * TT + gj] = niF[r][c] * rc;
            if (ti != tj)
                ob[(size_t)gj * TT + gi] = njF[r][c] * rc;
        }
    }
}

extern "C" void kernel_launch(void* const* d_in, const int* in_sizes, int n_in,
                              void* d_out, int out_size) {
    const float* x = (const float*)d_in[0];    // (8,512,64)
    const float* W = (const float*)d_in[1];    // (64,64)
    const float* bias = (const float*)d_in[2]; // (64,)
    float* out = (float*)d_out;                // (8,512,512)

    v_kernel<<<(BB * TT) / 32, 256>>>(x, W, bias);
    rbf_kernel<<<dim3(NPAIR, BB), 256>>>(out);
}

// round 15
// speedup vs baseline: 1.1405x; 1.1405x over previous
#include <cuda_runtime.h>
#include <cuda_fp16.h>

#define BB 8
#define TT 512
#define DD 64
#define TILE 32
#define NT (TT / TILE)               // 16 tiles per dim
#define NPAIR (NT * (NT + 1) / 2)    // 136 upper-tri tile pairs

#define SQRT_LOG2E 1.2011224087864498f
#define SGN2 0x80008000u

typedef unsigned long long u64;
typedef __half2 h2;

// Precomputed half-precision operands (written by v_kernel):
__device__ __half g_xh[BB * TT * DD];   // s * x   (256 KB)
__device__ __half g_vh[BB * TT * DD];   // v = xW^T + b (256 KB)

// ---- f16x2 helpers ---------------------------------------------------------
__device__ __forceinline__ h2 u2h(unsigned u) { return *(h2*)&u; }
__device__ __forceinline__ h2 ex2negsq(h2 dif) {
    h2 m = __hmul2(__hneg2(dif), dif);
    unsigned r, u = *(unsigned*)&m;
    asm("ex2.approx.f16x2 %0, %1;" : "=r"(r) : "r"(u));
    return *(h2*)&r;
}

// ---- HMMA helpers -----------------------------------------------------------
__device__ __forceinline__ void mma16816(float4& d,
    unsigned a0, unsigned a1, unsigned a2, unsigned a3,
    unsigned b0, unsigned b1) {
    asm("mma.sync.aligned.m16n8k16.row.col.f32.f16.f16.f32 "
        "{%0,%1,%2,%3}, {%4,%5,%6,%7}, {%8,%9}, {%0,%1,%2,%3};"
        : "+f"(d.x), "+f"(d.y), "+f"(d.z), "+f"(d.w)
        : "r"(a0), "r"(a1), "r"(a2), "r"(a3), "r"(b0), "r"(b1));
}
// Markidis split: w -> f16 high part + f16 residual (hi + lo ~= w to ~2^-22)
__device__ __forceinline__ void split2(float2 w, unsigned& hi, unsigned& lo) {
    h2 h = __floats2half2_rn(w.x, w.y);
    float2 bk = __half22float2(h);
    h2 l = __floats2half2_rn(w.x - bk.x, w.y - bk.y);
    hi = *(unsigned*)&h;
    lo = *(unsigned*)&l;
}

// ---------------------------------------------------------------------------
// Kernel 1: v = x @ W^T + b via HMMA (m16n8k16, f16 in, f32 accum) with
// split-precision correction: v = xh*Wh + xl*Wh + xh*Wl  (f32-accurate).
// Also emits g_xh = half(s*x). 32 blocks x 256 threads; warp w owns rows
// [blk*128 + 16w, +16). Fragments loaded directly from gmem (no smem).
// Writes g_vh = half(v).
// ---------------------------------------------------------------------------
__global__ __launch_bounds__(256)
void v_kernel(const float* __restrict__ x, const float* __restrict__ W,
              const float* __restrict__ bias) {
    int tid = threadIdx.x, bk = blockIdx.x;
    int rowB = bk * 128;

    // g_xh = half(s*x) for this block's 128 rows (4096 u32)
#pragma unroll
    for (int k = 0; k < 16; k++) {
        int lin = tid + 256 * k;
        int r = lin >> 5, q = lin & 31;
        float2 xx = *(const float2*)&x[(rowB + r) * DD + 2 * q];
        h2 hv = __floats2half2_rn(SQRT_LOG2E * xx.x, SQRT_LOG2E * xx.y);
        ((unsigned*)g_xh)[(rowB + r) * 32 + q] = *(unsigned*)&hv;
    }

    int lane = tid & 31, wid = tid >> 5;
    int g = lane >> 2, tq = lane & 3;     // groupID, thread-in-group
    int R = rowB + wid * 16;              // this warp's 16-row tile

    // A fragments (x rows), hi + lo, for 4 k-steps of 16
    unsigned ah[4][4], al[4][4];
#pragma unroll
    for (int ks = 0; ks < 4; ks++) {
        const float* b0 = x + (R + g) * DD + 16 * ks + 2 * tq;
        const float* b1 = x + (R + g + 8) * DD + 16 * ks + 2 * tq;
        split2(*(const float2*)(b0),     ah[ks][0], al[ks][0]);
        split2(*(const float2*)(b1),     ah[ks][1], al[ks][1]);
        split2(*(const float2*)(b0 + 8), ah[ks][2], al[ks][2]);
        split2(*(const float2*)(b1 + 8), ah[ks][3], al[ks][3]);
    }

#pragma unroll
    for (int nt = 0; nt < 8; nt++) {
        float4 acc = make_float4(0.f, 0.f, 0.f, 0.f);
        int e = 8 * nt + g;               // W row feeding B fragment
#pragma unroll
        for (int ks = 0; ks < 4; ks++) {
            unsigned bh0, bl0, bh1, bl1;
            split2(*(const float2*)&W[e * DD + 16 * ks + 2 * tq],     bh0, bl0);
            split2(*(const float2*)&W[e * DD + 16 * ks + 2 * tq + 8], bh1, bl1);
            mma16816(acc, ah[ks][0], ah[ks][1], ah[ks][2], ah[ks][3], bh0, bh1);
            mma16816(acc, al[ks][0], al[ks][1], al[ks][2], al[ks][3], bh0, bh1);
            mma16816(acc, ah[ks][0], ah[ks][1], ah[ks][2], ah[ks][3], bl0, bl1);
        }
        int e0 = 8 * nt + 2 * tq;         // D-fragment columns
        float bb0 = bias[e0], bb1 = bias[e0 + 1];
        h2 p0 = __floats2half2_rn(acc.x + bb0, acc.y + bb1);   // row R+g
        h2 p1 = __floats2half2_rn(acc.z + bb0, acc.w + bb1);   // row R+g+8
        ((unsigned*)g_vh)[(R + g) * 32 + 4 * nt + tq]     = *(unsigned*)&p0;
        ((unsigned*)g_vh)[(R + g + 8) * 32 + 4 * nt + tq] = *(unsigned*)&p1;
    }
}

// ---------------------------------------------------------------------------
// Kernel 2: pairwise RBF (EXACT R12 datapath — best known: 19.0us).
// d-PACKED f16x2 hot loop; per group: HADD2 + HMUL2(src-neg) + MUFU +
// HADD2 + 2x HFMA2. Thread (tx,ty): rows {2ty,2ty+1} x cols {tx, tx+16};
// [row][d] layout, j-arrays XOR-swizzled in 8B units -> conflict-free LDS.64.
// ---------------------------------------------------------------------------
#define OFF_VI  2048
#define OFF_NXJ 4096
#define OFF_VJ  6144

__global__ __launch_bounds__(256, 4)
void rbf_kernel(float* __restrict__ out) {
    __shared__ __align__(16) __half Sh[8192];   // 16 KB: XI | VI | NXJ | VJ

    int b = blockIdx.y;
    int p = blockIdx.x;
    int ti = 0, rem = p;
    while (rem >= NT - ti) { rem -= NT - ti; ti++; }
    int tj = ti + rem;
    int i0 = ti * TILE, j0 = tj * TILE;

    int tid = threadIdx.x;
    const unsigned* gx = (const unsigned*)g_xh;
    const unsigned* gv = (const unsigned*)g_vh;
    unsigned* S32 = (unsigned*)Sh;
    int baseI = (b * TT + i0) * 32;
    int baseJ = (b * TT + j0) * 32;

    {
        int r = tid >> 3, q0 = (tid & 7) * 4;
        int lin = r * 32 + q0;
        uint4 xi4 = *(const uint4*)&gx[baseI + lin];
        uint4 vi4 = *(const uint4*)&gv[baseI + lin];
        uint4 xj4 = *(const uint4*)&gx[baseJ + lin];
        uint4 vj4 = *(const uint4*)&gv[baseJ + lin];

        *(uint4*)&S32[lin] = xi4;                         // XI linear
        *(uint4*)&S32[(OFF_VI >> 1) + lin] = vi4;         // VI linear

        int msk = r & 15;
        int u0 = (q0 >> 1) ^ msk;
        int u1 = u0 ^ 1;
        *(uint2*)&S32[(OFF_NXJ >> 1) + r * 32 + 2 * u0] =
            make_uint2(xj4.x ^ SGN2, xj4.y ^ SGN2);       // -s*xj
        *(uint2*)&S32[(OFF_NXJ >> 1) + r * 32 + 2 * u1] =
            make_uint2(xj4.z ^ SGN2, xj4.w ^ SGN2);
        *(uint2*)&S32[(OFF_VJ >> 1) + r * 32 + 2 * u0] = make_uint2(vj4.x, vj4.y);
        *(uint2*)&S32[(OFF_VJ >> 1) + r * 32 + 2 * u1] = make_uint2(vj4.z, vj4.w);
    }
    __syncthreads();

    int tx = tid & 15, ty = tid >> 4;
    const __half* pi = Sh + 2 * ty * 64;
    const __half* pj = Sh + OFF_NXJ + tx * 64;

    float denF[2][2], niF[2][2], njF[2][2];
#pragma unroll
    for (int r = 0; r < 2; r++)
#pragma unroll
        for (int c = 0; c < 2; c++) { denF[r][c] = 0.f; niF[r][c] = 0.f; njF[r][c] = 0.f; }

#pragma unroll
    for (int ch = 0; ch < 2; ch++) {         // 2 chunks of 32 d
        h2 dH[2][2], nH[2][2], qH[2][2];
        h2 z = __float2half2_rn(0.f);
#pragma unroll
        for (int r = 0; r < 2; r++)
#pragma unroll
            for (int c = 0; c < 2; c++) { dH[r][c] = z; nH[r][c] = z; qH[r][c] = z; }

#pragma unroll
        for (int s = 0; s < 8; s++) {        // 4 d's per step
            int u = ch * 8 + s;
            int uj = u ^ tx;

            uint2 fiA = *(const uint2*)(pi + 4 * u);
            uint2 fiB = *(const uint2*)(pi + 64 + 4 * u);
            uint2 fvA = *(const uint2*)(pi + OFF_VI + 4 * u);
            uint2 fvB = *(const uint2*)(pi + OFF_VI + 64 + 4 * u);
            uint2 njA = *(const uint2*)(pj + 4 * uj);
            uint2 njB = *(const uint2*)(pj + 1024 + 4 * uj);
            uint2 jvA = *(const uint2*)(pj + 2048 + 4 * uj);
            uint2 jvB = *(const uint2*)(pj + 2048 + 1024 + 4 * uj);

            h2 fi[2][2] = {{u2h(fiA.x), u2h(fiA.y)}, {u2h(fiB.x), u2h(fiB.y)}};
            h2 fv[2][2] = {{u2h(fvA.x), u2h(fvA.y)}, {u2h(fvB.x), u2h(fvB.y)}};
            h2 nj[2][2] = {{u2h(njA.x), u2h(njA.y)}, {u2h(njB.x), u2h(njB.y)}};
            h2 jv[2][2] = {{u2h(jvA.x), u2h(jvA.y)}, {u2h(jvB.x), u2h(jvB.y)}};

#pragma unroll
            for (int r = 0; r < 2; r++)
#pragma unroll
                for (int c = 0; c < 2; c++)
#pragma unroll
                    for (int s2 = 0; s2 < 2; s2++) {
                        h2 dif = __hadd2(fi[r][s2], nj[c][s2]);
                        h2 e   = ex2negsq(dif);
                        dH[r][c] = __hadd2(dH[r][c], e);
                        nH[r][c] = __hfma2(e, fv[r][s2], nH[r][c]);
                        qH[r][c] = __hfma2(e, jv[c][s2], qH[r][c]);
                    }
        }

#pragma unroll
        for (int r = 0; r < 2; r++)
#pragma unroll
            for (int c = 0; c < 2; c++) {
                float2 t;
                t = __half22float2(dH[r][c]); denF[r][c] += t.x + t.y;
                t = __half22float2(nH[r][c]); niF[r][c]  += t.x + t.y;
                t = __half22float2(qH[r][c]); njF[r][c]  += t.x + t.y;
            }
    }

    float* ob = out + (size_t)b * TT * TT;

#pragma unroll
    for (int r = 0; r < 2; r++) {
        int gi = i0 + 2 * ty + r;
#pragma unroll
        for (int c = 0; c < 2; c++) {
            int gj = j0 + tx + 16 * c;
            float rc;
            asm("rcp.approx.ftz.f32 %0, %1;" : "=f"(rc) : "f"(denF[r][c]));
            ob[(size_t)gi * TT + gj] = niF[r][c] * rc;
            if (ti != tj)
                ob[(size_t)gj * TT + gi] = njF[r][c] * rc;
        }
    }
}

extern "C" void kernel_launch(void* const* d_in, const int* in_sizes, int n_in,
                              void* d_out, int out_size) {
    const float* x = (const float*)d_in[0];    // (8,512,64)
    const float* W = (const float*)d_in[1];    // (64,64)
    const float* bias = (const float*)d_in[2]; // (64,)
    float* out = (float*)d_out;                // (8,512,512)

    v_kernel<<<(BB * TT) / 128, 256>>>(x, W, bias);
    rbf_kernel<<<dim3(NPAIR, BB), 256>>>(out);
}